// round 15
// baseline (speedup 1.0000x reference)
#include <cuda_runtime.h>
#include <cuda_fp16.h>
#include <cstdint>

// Problem constants
#define B_  256
#define O_  128
#define H_  1024
#define HH  512
#define I_  2048
#define DFF 1536

typedef unsigned long long u64;

// ---------------- device scratch ----------------
__device__ __align__(16) float g_hW[8 * B_ * HH];      // split-K=8 partials of h@W_e^T (+b_e slice0)
__device__ __align__(16) float g_partial[B_ * O_ * 4]; // score partials
__device__ __align__(16) __half g_xjh[B_ * O_ * HH];   // x_j in fp16 (32MB)
__device__ __align__(16) __half g_UeH[HH * HH];        // U_e fp16
__device__ __align__(16) __half g_wh[4u * 1024u * 4096u]; // gate weights fp16, virtual-K layout (32MB)
__device__ __align__(16) __half g_zh[B_ * 4096];       // [phi|X_F|h|c] fp16
__device__ __align__(16) float g_gp[4 * B_ * 4096];    // split-K=4 gate partials
__device__ int g_mflag;

// ---------------- helpers ----------------
__device__ __forceinline__ uint32_t smem_u32(const void* p) {
    uint32_t a;
    asm("{ .reg .u64 t; cvta.to.shared.u64 t, %1; cvt.u32.u64 %0, t; }" : "=r"(a) : "l"(p));
    return a;
}
__device__ __forceinline__ uint32_t swz(uint32_t off) { return off ^ ((off >> 3) & 0x70); }

__device__ __forceinline__ void ldsm4(uint32_t* r, uint32_t addr) {
    asm volatile("ldmatrix.sync.aligned.m8n8.x4.shared.b16 {%0,%1,%2,%3},[%4];"
        : "=r"(r[0]), "=r"(r[1]), "=r"(r[2]), "=r"(r[3]) : "r"(addr));
}
__device__ __forceinline__ void mma16816(float* c, const uint32_t* a, const uint32_t* b) {
    asm volatile("mma.sync.aligned.m16n8k16.row.col.f32.f16.f16.f32 "
        "{%0,%1,%2,%3},{%4,%5,%6,%7},{%8,%9},{%0,%1,%2,%3};"
        : "+f"(c[0]), "+f"(c[1]), "+f"(c[2]), "+f"(c[3])
        : "r"(a[0]), "r"(a[1]), "r"(a[2]), "r"(a[3]), "r"(b[0]), "r"(b[1]));
}
__device__ __forceinline__ void cp16(uint32_t dst, const void* src) {
    asm volatile("cp.async.cg.shared.global [%0],[%1],16;" :: "r"(dst), "l"(src));
}
#define CP_COMMIT() asm volatile("cp.async.commit_group;" ::: "memory")
#define CP_WAIT0()  asm volatile("cp.async.wait_group 0;" ::: "memory")

__device__ __forceinline__ uint32_t pk2(float a, float b) {
    __half2 x = __floats2half2_rn(a, b);
    uint32_t r; memcpy(&r, &x, 4); return r;
}
__device__ __forceinline__ float sigmoidf_(float x) { return 1.0f / (1.0f + expf(-x)); }

// ---------------- kernel 1: fused preamble ----------------
// blocks [0,8192): cvt_xj    [8192,8320): cvt_ue    [8320,12416): cvt weights
// [12416,12672): hW split-K=8    block 12672: mask sniff
__global__ void __launch_bounds__(256, 2)
k_pre(const float* __restrict__ xj, const float* __restrict__ Ue,
      const float* __restrict__ h, const float* __restrict__ We,
      const float* __restrict__ be, const unsigned char* __restrict__ mk,
      const float* __restrict__ Wi, const float* __restrict__ Wf,
      const float* __restrict__ Wc, const float* __restrict__ Wo,
      const float* __restrict__ Ui, const float* __restrict__ Uf,
      const float* __restrict__ Uc, const float* __restrict__ Uo,
      const float* __restrict__ Vi, const float* __restrict__ Vf,
      const float* __restrict__ Vo) {
    __shared__ __align__(16) float As[2][8][64];
    __shared__ __align__(16) float Bs[2][8][64];
    int bid = blockIdx.x;
    int t = threadIdx.x;

    if (bid < 8192) {
        // ---- cvt x_j -> fp16 ----
        size_t i = ((size_t)bid * 256 + t) * 8;
        float4 v0 = *(const float4*)(xj + i);
        float4 v1 = *(const float4*)(xj + i + 4);
        uint4 o;
        o.x = pk2(v0.x, v0.y); o.y = pk2(v0.z, v0.w);
        o.z = pk2(v1.x, v1.y); o.w = pk2(v1.z, v1.w);
        *(uint4*)(g_xjh + i) = o;
        return;
    }
    if (bid < 8320) {
        // ---- cvt U_e -> fp16 ----
        size_t i = ((size_t)(bid - 8192) * 256 + t) * 8;
        float4 v0 = *(const float4*)(Ue + i);
        float4 v1 = *(const float4*)(Ue + i + 4);
        uint4 hi;
        hi.x = pk2(v0.x, v0.y); hi.y = pk2(v0.z, v0.w);
        hi.z = pk2(v1.x, v1.y); hi.w = pk2(v1.z, v1.w);
        *(uint4*)(g_UeH + i) = hi;
        return;
    }
    if (bid < 12416) {
        // ---- cvt gate weights -> fp16 virtual-K rows ----
        // row r = bid-8320 in [0,4096): gg = r>>10, j = r&1023.
        // out row g_wh[r*4096 + kk]: kk<2048 -> W_g[j][kk]; kk<3072 -> U_g[j][kk-2048];
        // else V_g[j][kk-3072] (zero when gg==2).
        int r = bid - 8320;
        int gg = r >> 10, j = r & 1023;
        const float* Wg = (gg == 0) ? Wi : (gg == 1) ? Wf : (gg == 2) ? Wc : Wo;
        const float* Ug = (gg == 0) ? Ui : (gg == 1) ? Uf : (gg == 2) ? Uc : Uo;
        const float* Vg = (gg == 0) ? Vi : (gg == 1) ? Vf : (gg == 3) ? Vo : nullptr;
        __half* orow = g_wh + (size_t)r * 4096;
        int kk = t * 16;  // 16 elems per thread, 256 threads = 4096
        float4 v0, v1, v2, v3;
        if (kk < 2048) {
            const float* p = Wg + (size_t)j * 2048 + kk;
            v0 = *(const float4*)p; v1 = *(const float4*)(p + 4);
            v2 = *(const float4*)(p + 8); v3 = *(const float4*)(p + 12);
        } else if (kk < 3072) {
            const float* p = Ug + (size_t)j * 1024 + (kk - 2048);
            v0 = *(const float4*)p; v1 = *(const float4*)(p + 4);
            v2 = *(const float4*)(p + 8); v3 = *(const float4*)(p + 12);
        } else if (Vg) {
            const float* p = Vg + (size_t)j * 1024 + (kk - 3072);
            v0 = *(const float4*)p; v1 = *(const float4*)(p + 4);
            v2 = *(const float4*)(p + 8); v3 = *(const float4*)(p + 12);
        } else {
            v0 = v1 = v2 = v3 = make_float4(0, 0, 0, 0);
        }
        uint4 o0, o1;
        o0.x = pk2(v0.x, v0.y); o0.y = pk2(v0.z, v0.w);
        o0.z = pk2(v1.x, v1.y); o0.w = pk2(v1.z, v1.w);
        o1.x = pk2(v2.x, v2.y); o1.y = pk2(v2.z, v2.w);
        o1.z = pk2(v3.x, v3.y); o1.w = pk2(v3.z, v3.w);
        *(uint4*)(orow + kk) = o0;
        *(uint4*)(orow + kk + 8) = o1;
        return;
    }
    if (bid == 12672) {
        // ---- mask dtype sniff ----
        __shared__ int anyBig, off123;
        if (t == 0) { anyBig = 0; off123 = 0; }
        __syncthreads();
        int big = 0, o123 = 0;
        for (int i = t; i < 4096; i += 256) {
            unsigned char v = mk[i];
            if (v >= 2) big = 1;
            if ((i & 3) != 0 && v != 0) o123 = 1;
        }
        if (big) atomicOr(&anyBig, 1);
        if (o123) atomicOr(&off123, 1);
        __syncthreads();
        if (t == 0) g_mflag = anyBig ? 1 : (off123 ? 0 : 2);
        return;
    }

    // ---- hW partials = h @ W_e^T, split-K=8 (FFMA2) ----
    int idx = bid - 12416;             // 0..255
    int n0 = (idx & 7) * 64;           // 8 n-tiles
    int m0 = ((idx >> 3) & 3) * 64;    // 4 m-tiles
    int ks = idx >> 5;                 // 8 K slices of 128
    int tx = t & 15, ty = t >> 4;
    int lr = t >> 1, lp = (t & 1) * 4;
    const float* Ap = h  + (m0 + lr) * H_ + ks * 128 + lp;
    const float* Bp = We + (n0 + lr) * H_ + ks * 128 + lp;

    u64 acc[4][2] = {};
    float4 a4 = make_float4(0,0,0,0), b4 = make_float4(0,0,0,0);
    if (t < 128) { a4 = *(const float4*)Ap; b4 = *(const float4*)Bp; }
    if (t < 128) {
        As[0][lp+0][lr]=a4.x; As[0][lp+1][lr]=a4.y; As[0][lp+2][lr]=a4.z; As[0][lp+3][lr]=a4.w;
        Bs[0][lp+0][lr]=b4.x; Bs[0][lp+1][lr]=b4.y; Bs[0][lp+2][lr]=b4.z; Bs[0][lp+3][lr]=b4.w;
    }
    __syncthreads();
    int buf = 0;
    const int KT = 128 / 8;
    for (int kt = 0; kt < KT; kt++) {
        if (kt < KT - 1 && t < 128) {
            a4 = *(const float4*)(Ap + (kt + 1) * 8);
            b4 = *(const float4*)(Bp + (kt + 1) * 8);
        }
#pragma unroll
        for (int kk = 0; kk < 8; kk++) {
            float4 av = *(const float4*)&As[buf][kk][ty * 4];
            u64 b0 = *(const u64*)&Bs[buf][kk][tx * 4];
            u64 b1 = *(const u64*)&Bs[buf][kk][tx * 4 + 2];
            u64 ap;
            asm("mov.b64 %0,{%1,%1};" : "=l"(ap) : "f"(av.x));
            asm("fma.rn.f32x2 %0,%1,%2,%0;" : "+l"(acc[0][0]) : "l"(ap), "l"(b0));
            asm("fma.rn.f32x2 %0,%1,%2,%0;" : "+l"(acc[0][1]) : "l"(ap), "l"(b1));
            asm("mov.b64 %0,{%1,%1};" : "=l"(ap) : "f"(av.y));
            asm("fma.rn.f32x2 %0,%1,%2,%0;" : "+l"(acc[1][0]) : "l"(ap), "l"(b0));
            asm("fma.rn.f32x2 %0,%1,%2,%0;" : "+l"(acc[1][1]) : "l"(ap), "l"(b1));
            asm("mov.b64 %0,{%1,%1};" : "=l"(ap) : "f"(av.z));
            asm("fma.rn.f32x2 %0,%1,%2,%0;" : "+l"(acc[2][0]) : "l"(ap), "l"(b0));
            asm("fma.rn.f32x2 %0,%1,%2,%0;" : "+l"(acc[2][1]) : "l"(ap), "l"(b1));
            asm("mov.b64 %0,{%1,%1};" : "=l"(ap) : "f"(av.w));
            asm("fma.rn.f32x2 %0,%1,%2,%0;" : "+l"(acc[3][0]) : "l"(ap), "l"(b0));
            asm("fma.rn.f32x2 %0,%1,%2,%0;" : "+l"(acc[3][1]) : "l"(ap), "l"(b1));
        }
        if (kt < KT - 1) {
            int nb = buf ^ 1;
            if (t < 128) {
                As[nb][lp+0][lr]=a4.x; As[nb][lp+1][lr]=a4.y; As[nb][lp+2][lr]=a4.z; As[nb][lp+3][lr]=a4.w;
                Bs[nb][lp+0][lr]=b4.x; Bs[nb][lp+1][lr]=b4.y; Bs[nb][lp+2][lr]=b4.z; Bs[nb][lp+3][lr]=b4.w;
            }
            buf = nb;
        }
        __syncthreads();
    }
    float* outp = g_hW + (size_t)ks * B_ * HH;
#pragma unroll
    for (int i = 0; i < 4; i++) {
        int row = m0 + ty * 4 + i;
#pragma unroll
        for (int jp = 0; jp < 2; jp++) {
            float l, hv;
            asm("mov.b64 {%0,%1},%2;" : "=f"(l), "=f"(hv) : "l"(acc[i][jp]));
            int c0 = n0 + tx * 4 + jp * 2;
            float bb0 = (ks == 0) ? be[c0] : 0.f;
            float bb1 = (ks == 0) ? be[c0 + 1] : 0.f;
            outp[row * HH + c0]     = l  + bb0;
            outp[row * HH + c0 + 1] = hv + bb1;
        }
    }
}

// ================== mma core: single-term fp16 ==================
// buffer: A(0..16K) BH(16K..32K); BUFSZ_S=32K, double-buffered
#define B_HI  16384u
#define BUFSZ_S 32768u

__device__ __forceinline__ void mma_chunk1(float acc[2][8][4], uint32_t bb,
                                           int wm, int wn, int lane) {
#pragma unroll
    for (int ks = 0; ks < 4; ks++) {
        uint32_t bh[4][4];
        int mm = lane >> 3, ch = mm & 1;
        int rhalf = ((mm >> 1) << 3) + (lane & 7);
#pragma unroll
        for (int p = 0; p < 4; p++) {
            uint32_t off = (uint32_t)(wn * 64 + p * 16 + rhalf) * 128 + ks * 32 + ch * 16;
            ldsm4(bh[p], bb + B_HI + swz(off));
        }
#pragma unroll
        for (int mt = 0; mt < 2; mt++) {
            uint32_t offa = (uint32_t)(wm * 32 + mt * 16 + (lane & 15)) * 128
                          + ks * 32 + (lane >> 4) * 16;
            uint32_t ah[4];
            ldsm4(ah, bb + swz(offa));
#pragma unroll
            for (int nt = 0; nt < 8; nt++)
                mma16816(acc[mt][nt], ah, &bh[nt >> 1][(nt & 1) * 2]);
        }
    }
}

// ---------------- kernel 2: scores GEMM (single-term fp16, occ 2) ----------------
// grid (4, 256): nq = 128-col quarter of U_e, b = batch. M = 128 objects, K=512.
__global__ void __launch_bounds__(256, 2)
k_scores_mma(const float* __restrict__ w) {
    extern __shared__ __align__(1024) char smem[];
    uint32_t S = smem_u32(smem);
    const int t = threadIdx.x, wid = t >> 5, lane = t & 31;
    const int wm = wid >> 1, wn = wid & 1;
    const int nq = blockIdx.x, b = blockIdx.y;
    const int n0 = nq * 128;

    const uint32_t OFF_HW = 0, OFF_W = 512, OFF_RS = 1024, OFF_BUF = 2048;
    float* hWs = (float*)(smem + OFF_HW);
    float* ws  = (float*)(smem + OFF_W);
    float* rs  = (float*)(smem + OFF_RS);

    if (t < 128) {
        int idx = b * HH + n0 + t;
        float s8 = 0.f;
#pragma unroll
        for (int sk = 0; sk < 8; sk++) s8 += g_hW[(size_t)sk * B_ * HH + idx];
        hWs[t] = s8;
        ws[t] = w[n0 + t];
    }

    const int row_ = t >> 1;                  // 0..127 (thread pairs per row)
    const int c8a = (t & 1) * 4;              // base 16B-chunk within row half
    auto prefetch = [&](int kc, int buf) {
        uint32_t Sb = S + OFF_BUF + buf * BUFSZ_S;
        const __half* Asrc = g_xjh + (size_t)(b * O_ + row_) * HH + kc * 64;
        const __half* BHsrc = g_UeH + (size_t)(n0 + row_) * HH + kc * 64;
#pragma unroll
        for (int j = 0; j < 4; j++) {
            uint32_t off = swz((uint32_t)row_ * 128 + (c8a + j) * 16);
            cp16(Sb + off,        Asrc + (c8a + j) * 8);
            cp16(Sb + B_HI + off, BHsrc + (c8a + j) * 8);
        }
        CP_COMMIT();
    };

    float acc[2][8][4] = {};
    prefetch(0, 0);
    for (int c = 0; c < 8; c++) {
        CP_WAIT0();
        __syncthreads();
        if (c + 1 < 8) prefetch(c + 1, (c + 1) & 1);
        mma_chunk1(acc, S + OFF_BUF + (c & 1) * BUFSZ_S, wm, wn, lane);
    }

    // epilogue: tanh(C + hW) * w, reduce over 128 cols
    int g = lane >> 2, q = lane & 3;
#pragma unroll
    for (int mt = 0; mt < 2; mt++) {
        float sA = 0.f, sB = 0.f;
#pragma unroll
        for (int nt = 0; nt < 8; nt++) {
            int col = wn * 64 + nt * 8 + q * 2;
            sA += tanhf(acc[mt][nt][0] + hWs[col])     * ws[col];
            sA += tanhf(acc[mt][nt][1] + hWs[col + 1]) * ws[col + 1];
            sB += tanhf(acc[mt][nt][2] + hWs[col])     * ws[col];
            sB += tanhf(acc[mt][nt][3] + hWs[col + 1]) * ws[col + 1];
        }
        sA += __shfl_xor_sync(0xffffffffu, sA, 1);
        sA += __shfl_xor_sync(0xffffffffu, sA, 2);
        sB += __shfl_xor_sync(0xffffffffu, sB, 1);
        sB += __shfl_xor_sync(0xffffffffu, sB, 2);
        if (q == 0) {
            int r0 = wm * 32 + mt * 16 + g;
            rs[wn * 128 + r0]     = sA;
            rs[wn * 128 + r0 + 8] = sB;
        }
    }
    __syncthreads();
    if (t < 128)
        g_partial[(b * O_ + t) * 4 + nq] = rs[t] + rs[128 + t];
}

// ---------------- kernel 3: fused softmax + phi (o-split x2) + z-gather ----------------
__global__ void __launch_bounds__(1024, 1)
k_attn_z(const void* __restrict__ mask, const float* __restrict__ XF,
         const float* __restrict__ h, const float* __restrict__ c) {
    __shared__ float sa[128], redm[128], reds[128];
    __shared__ float phis2[2][512];
    int b = blockIdx.x, t = threadIdx.x;  // 1024 threads
    float s = 0.f, e = 0.f;
    if (t < 128) {
        const float* pr = g_partial + (b * O_ + t) * 4;
        s = pr[0] + pr[1] + pr[2] + pr[3];
        int mf = g_mflag;
        bool mv;
        int mi = b * O_ + t;
        if (mf == 1)      mv = ((const float*)mask)[mi] != 0.0f;
        else if (mf == 2) mv = ((const int*)mask)[mi] != 0;
        else              mv = ((const unsigned char*)mask)[mi] != 0;
        if (!mv) s = -1e9f;
        redm[t] = s;
    }
    __syncthreads();
    for (int off = 64; off > 0; off >>= 1) {
        if (t < off) redm[t] = fmaxf(redm[t], redm[t + off]);
        __syncthreads();
    }
    float mx = redm[0];
    if (t < 128) { e = expf(s - mx); reds[t] = e; }
    __syncthreads();
    for (int off = 64; off > 0; off >>= 1) {
        if (t < off) reds[t] += reds[t + off];
        __syncthreads();
    }
    if (t < 128) sa[t] = e / reds[0];
    __syncthreads();

    // phi: 2-way o-split; thread (half, col) sums 64 objects for its column
    {
        int half = t >> 9;        // 0/1
        int col  = t & 511;
        float acc = 0.f;
        const __half* X = g_xjh + (size_t)b * O_ * HH + (size_t)half * 64 * HH;
        const float* sah = sa + half * 64;
#pragma unroll 4
        for (int o = 0; o < 64; o++)
            acc += sah[o] * __half2float(X[(size_t)o * HH + col]);
        phis2[half][col] = acc;
    }
    __syncthreads();

    // z fp16: threads 0..511, 8 elems each
    if (t < 512) {
        int j0 = t * 8;
        float v[8];
        if (j0 < 512) {
#pragma unroll
            for (int k = 0; k < 8; k++) v[k] = phis2[0][j0 + k] + phis2[1][j0 + k];
        } else if (j0 < 2048) {
            const float* p = XF + (size_t)b * DFF + (j0 - 512);
            float4 a = *(const float4*)p, bq = *(const float4*)(p + 4);
            v[0]=a.x; v[1]=a.y; v[2]=a.z; v[3]=a.w; v[4]=bq.x; v[5]=bq.y; v[6]=bq.z; v[7]=bq.w;
        } else if (j0 < 3072) {
            const float* p = h + (size_t)b * H_ + (j0 - 2048);
            float4 a = *(const float4*)p, bq = *(const float4*)(p + 4);
            v[0]=a.x; v[1]=a.y; v[2]=a.z; v[3]=a.w; v[4]=bq.x; v[5]=bq.y; v[6]=bq.z; v[7]=bq.w;
        } else {
            const float* p = c + (size_t)b * H_ + (j0 - 3072);
            float4 a = *(const float4*)p, bq = *(const float4*)(p + 4);
            v[0]=a.x; v[1]=a.y; v[2]=a.z; v[3]=a.w; v[4]=bq.x; v[5]=bq.y; v[6]=bq.z; v[7]=bq.w;
        }
        uint4 o;
        o.x = pk2(v[0], v[1]); o.y = pk2(v[2], v[3]);
        o.z = pk2(v[4], v[5]); o.w = pk2(v[6], v[7]);
        *(uint4*)(g_zh + (size_t)b * 4096 + j0) = o;
    }
}

// ---------------- kernel 4: gates GEMM (pure cp.async fp16, split-K=4, occ 2) -------
// grid (32, 2, 4): bx = n-block(128), by = m-block(128), bz = K slice (1024)
__global__ void __launch_bounds__(256, 2)
k_gates_mma() {
    extern __shared__ __align__(1024) char smem[];
    uint32_t S = smem_u32(smem);
    const int t = threadIdx.x, wid = t >> 5, lane = t & 31;
    const int wm = wid >> 1, wn = wid & 1;
    const int nb_ = blockIdx.x, mb = blockIdx.y, ksp = blockIdx.z;
    const int n0g = nb_ * 128;

    const int row_ = t >> 1;
    const int c8a = (t & 1) * 4;
    auto prefetch = [&](int kc, int buf) {
        uint32_t Sb = S + buf * BUFSZ_S;
        const __half* Asrc = g_zh + (size_t)(mb * 128 + row_) * 4096
                           + ksp * 1024 + kc * 64;
        const __half* Bsrc = g_wh + (size_t)(n0g + row_) * 4096
                           + ksp * 1024 + kc * 64;
#pragma unroll
        for (int j = 0; j < 4; j++) {
            uint32_t off = swz((uint32_t)row_ * 128 + (c8a + j) * 16);
            cp16(Sb + off,        Asrc + (c8a + j) * 8);
            cp16(Sb + B_HI + off, Bsrc + (c8a + j) * 8);
        }
        CP_COMMIT();
    };

    float acc[2][8][4] = {};
    prefetch(0, 0);
    for (int c = 0; c < 16; c++) {
        CP_WAIT0();
        __syncthreads();
        if (c + 1 < 16) prefetch(c + 1, (c + 1) & 1);
        mma_chunk1(acc, S + (c & 1) * BUFSZ_S, wm, wn, lane);
    }

    // epilogue: store fp32 partials
    int g = lane >> 2, q = lane & 3;
#pragma unroll
    for (int mt = 0; mt < 2; mt++) {
        int m = mb * 128 + wm * 32 + mt * 16 + g;
        float* baseA = g_gp + (size_t)(ksp * B_ + m) * 4096 + n0g;
        float* baseB = g_gp + (size_t)(ksp * B_ + m + 8) * 4096 + n0g;
#pragma unroll
        for (int nt = 0; nt < 8; nt++) {
            int col = wn * 64 + nt * 8 + q * 2;
            *(float2*)(baseA + col) = make_float2(acc[mt][nt][0], acc[mt][nt][1]);
            *(float2*)(baseB + col) = make_float2(acc[mt][nt][2], acc[mt][nt][3]);
        }
    }
}

// ---------------- kernel 5: elementwise LSTM update ----------------
__global__ void k_final(const float* __restrict__ c,
                        const float* __restrict__ bi, const float* __restrict__ bf,
                        const float* __restrict__ bc, const float* __restrict__ bo,
                        float* __restrict__ out) {
    int idx = blockIdx.x * 256 + threadIdx.x;
    int b = idx >> 10, j = idx & 1023;
    const float* g0 = g_gp + (size_t)b * 4096;
    const float* g1 = g_gp + (size_t)(B_ + b) * 4096;
    const float* g2 = g_gp + (size_t)(2 * B_ + b) * 4096;
    const float* g3 = g_gp + (size_t)(3 * B_ + b) * 4096;
    float gi = g0[j]        + g1[j]        + g2[j]        + g3[j]        + bi[j];
    float gf = g0[1024 + j] + g1[1024 + j] + g2[1024 + j] + g3[1024 + j] + bf[j];
    float gc = g0[2048 + j] + g1[2048 + j] + g2[2048 + j] + g3[2048 + j] + bc[j];
    float go = g0[3072 + j] + g1[3072 + j] + g2[3072 + j] + g3[3072 + j] + bo[j];
    float si = sigmoidf_(gi);
    float sf = sigmoidf_(gf);
    float so = sigmoidf_(go);
    float cold = c[idx];
    float nc = sf * cold + si * tanhf(gc);
    float nh = so * tanhf(nc);
    out[idx] = nh;
    out[B_ * H_ + idx] = nc;
}

// ---------------- launch ----------------
extern "C" void kernel_launch(void* const* d_in, const int* in_sizes, int n_in,
                              void* d_out, int out_size) {
    const float* x_j  = (const float*)d_in[0];
    const void*  mask = d_in[1];
    const float* X_F  = (const float*)d_in[2];
    const float* h    = (const float*)d_in[3];
    const float* c    = (const float*)d_in[4];
    const float* W_i  = (const float*)d_in[5];
    const float* W_f  = (const float*)d_in[6];
    const float* W_c  = (const float*)d_in[7];
    const float* W_o  = (const float*)d_in[8];
    const float* U_i  = (const float*)d_in[9];
    const float* U_f  = (const float*)d_in[10];
    const float* U_c  = (const float*)d_in[11];
    const float* U_o  = (const float*)d_in[12];
    const float* V_i  = (const float*)d_in[13];
    const float* V_f  = (const float*)d_in[14];
    const float* V_o  = (const float*)d_in[16];
    const float* b_i  = (const float*)d_in[17];
    const float* b_f  = (const float*)d_in[18];
    const float* b_c  = (const float*)d_in[19];
    const float* b_o  = (const float*)d_in[20];
    const float* w    = (const float*)d_in[21];
    const float* W_e  = (const float*)d_in[22];
    const float* U_e  = (const float*)d_in[23];
    const float* b_e  = (const float*)d_in[24];

    cudaFuncSetAttribute(k_scores_mma, cudaFuncAttributeMaxDynamicSharedMemorySize, 67584);
    cudaFuncSetAttribute(k_gates_mma,  cudaFuncAttributeMaxDynamicSharedMemorySize, 65536);

    k_pre<<<12673, 256>>>(x_j, U_e, h, W_e, b_e, (const unsigned char*)mask,
                          W_i, W_f, W_c, W_o, U_i, U_f, U_c, U_o, V_i, V_f, V_o);
    k_scores_mma<<<dim3(4, 256), 256, 67584>>>(w);
    k_attn_z<<<256, 1024>>>(mask, X_F, h, c);
    k_gates_mma<<<dim3(32, 2, 4), 256, 65536>>>();
    k_final<<<1024, 256>>>(c, b_i, b_f, b_c, b_o, (float*)d_out);
}

// round 16
// speedup vs baseline: 1.0712x; 1.0712x over previous
#include <cuda_runtime.h>
#include <cuda_fp16.h>
#include <cstdint>

// Problem constants
#define B_  256
#define O_  128
#define H_  1024
#define HH  512
#define I_  2048
#define DFF 1536

typedef unsigned long long u64;

// ---------------- device scratch ----------------
__device__ __align__(16) float g_hW[8 * B_ * HH];      // split-K=8 partials of h@W_e^T (+b_e slice0)
__device__ __align__(16) float g_partial[B_ * O_ * 4]; // score partials
__device__ __align__(16) __half g_xjh[B_ * O_ * HH];   // x_j in fp16 (32MB)
__device__ __align__(16) __half g_UeH[HH * HH];        // U_e fp16
__device__ __align__(16) __half g_zh[B_ * 4096];       // [phi|X_F|h|c] fp16
__device__ __align__(16) float g_gp[4 * B_ * 4096];    // split-K=4 gate partials
__device__ int g_mflag;

// ---------------- helpers ----------------
__device__ __forceinline__ uint32_t smem_u32(const void* p) {
    uint32_t a;
    asm("{ .reg .u64 t; cvta.to.shared.u64 t, %1; cvt.u32.u64 %0, t; }" : "=r"(a) : "l"(p));
    return a;
}
__device__ __forceinline__ uint32_t swz(uint32_t off) { return off ^ ((off >> 3) & 0x70); }

__device__ __forceinline__ void ldsm4(uint32_t* r, uint32_t addr) {
    asm volatile("ldmatrix.sync.aligned.m8n8.x4.shared.b16 {%0,%1,%2,%3},[%4];"
        : "=r"(r[0]), "=r"(r[1]), "=r"(r[2]), "=r"(r[3]) : "r"(addr));
}
__device__ __forceinline__ void mma16816(float* c, const uint32_t* a, const uint32_t* b) {
    asm volatile("mma.sync.aligned.m16n8k16.row.col.f32.f16.f16.f32 "
        "{%0,%1,%2,%3},{%4,%5,%6,%7},{%8,%9},{%0,%1,%2,%3};"
        : "+f"(c[0]), "+f"(c[1]), "+f"(c[2]), "+f"(c[3])
        : "r"(a[0]), "r"(a[1]), "r"(a[2]), "r"(a[3]), "r"(b[0]), "r"(b[1]));
}
__device__ __forceinline__ void cp16(uint32_t dst, const void* src) {
    asm volatile("cp.async.cg.shared.global [%0],[%1],16;" :: "r"(dst), "l"(src));
}
#define CP_COMMIT() asm volatile("cp.async.commit_group;" ::: "memory")
#define CP_WAIT0()  asm volatile("cp.async.wait_group 0;" ::: "memory")

__device__ __forceinline__ uint32_t pk2(float a, float b) {
    __half2 x = __floats2half2_rn(a, b);
    uint32_t r; memcpy(&r, &x, 4); return r;
}
__device__ __forceinline__ float sigmoidf_(float x) { return 1.0f / (1.0f + expf(-x)); }

// fp16 (round-nearest) of a float4, stored swizzled as u64
__device__ __forceinline__ void cvt_f16h(char* hib, uint32_t off, float4 v) {
    uint32_t so = swz(off);
    uint32_t h0 = pk2(v.x, v.y);
    uint32_t h1 = pk2(v.z, v.w);
    *(u64*)(hib + so) = (u64)h0 | ((u64)h1 << 32);
}

// ---------------- kernel 1: fused preamble (hW blocks FIRST) ----------------
// blocks [0,256): hW split-K=8   [256,8448): cvt_xj   [8448,8576): cvt_ue
// block 8576: mask sniff
__global__ void __launch_bounds__(256, 2)
k_pre(const float* __restrict__ xj, const float* __restrict__ Ue,
      const float* __restrict__ h, const float* __restrict__ We,
      const float* __restrict__ be, const unsigned char* __restrict__ mk) {
    __shared__ __align__(16) float As[2][8][64];
    __shared__ __align__(16) float Bs[2][8][64];
    int bid = blockIdx.x;
    int t = threadIdx.x;

    if (bid >= 256) {
        if (bid < 8448) {
            // ---- cvt x_j -> fp16 ----
            size_t i = ((size_t)(bid - 256) * 256 + t) * 8;
            float4 v0 = *(const float4*)(xj + i);
            float4 v1 = *(const float4*)(xj + i + 4);
            uint4 o;
            o.x = pk2(v0.x, v0.y); o.y = pk2(v0.z, v0.w);
            o.z = pk2(v1.x, v1.y); o.w = pk2(v1.z, v1.w);
            *(uint4*)(g_xjh + i) = o;
        } else if (bid < 8576) {
            // ---- cvt U_e -> fp16 ----
            size_t i = ((size_t)(bid - 8448) * 256 + t) * 8;
            float4 v0 = *(const float4*)(Ue + i);
            float4 v1 = *(const float4*)(Ue + i + 4);
            uint4 hi;
            hi.x = pk2(v0.x, v0.y); hi.y = pk2(v0.z, v0.w);
            hi.z = pk2(v1.x, v1.y); hi.w = pk2(v1.z, v1.w);
            *(uint4*)(g_UeH + i) = hi;
        } else {
            // ---- mask dtype sniff ----
            __shared__ int anyBig, off123;
            if (t == 0) { anyBig = 0; off123 = 0; }
            __syncthreads();
            int big = 0, o123 = 0;
            for (int i = t; i < 4096; i += 256) {
                unsigned char v = mk[i];
                if (v >= 2) big = 1;
                if ((i & 3) != 0 && v != 0) o123 = 1;
            }
            if (big) atomicOr(&anyBig, 1);
            if (o123) atomicOr(&off123, 1);
            __syncthreads();
            if (t == 0) g_mflag = anyBig ? 1 : (off123 ? 0 : 2);
        }
        return;
    }

    // ---- hW partials = h @ W_e^T, split-K=8 (FFMA2), bids 0..255 ----
    int idx = bid;
    int n0 = (idx & 7) * 64;           // 8 n-tiles
    int m0 = ((idx >> 3) & 3) * 64;    // 4 m-tiles
    int ks = idx >> 5;                 // 8 K slices of 128
    int tx = t & 15, ty = t >> 4;
    int lr = t >> 1, lp = (t & 1) * 4;
    const float* Ap = h  + (m0 + lr) * H_ + ks * 128 + lp;
    const float* Bp = We + (n0 + lr) * H_ + ks * 128 + lp;

    u64 acc[4][2] = {};
    float4 a4 = make_float4(0,0,0,0), b4 = make_float4(0,0,0,0);
    if (t < 128) { a4 = *(const float4*)Ap; b4 = *(const float4*)Bp; }
    if (t < 128) {
        As[0][lp+0][lr]=a4.x; As[0][lp+1][lr]=a4.y; As[0][lp+2][lr]=a4.z; As[0][lp+3][lr]=a4.w;
        Bs[0][lp+0][lr]=b4.x; Bs[0][lp+1][lr]=b4.y; Bs[0][lp+2][lr]=b4.z; Bs[0][lp+3][lr]=b4.w;
    }
    __syncthreads();
    int buf = 0;
    const int KT = 128 / 8;
    for (int kt = 0; kt < KT; kt++) {
        if (kt < KT - 1 && t < 128) {
            a4 = *(const float4*)(Ap + (kt + 1) * 8);
            b4 = *(const float4*)(Bp + (kt + 1) * 8);
        }
#pragma unroll
        for (int kk = 0; kk < 8; kk++) {
            float4 av = *(const float4*)&As[buf][kk][ty * 4];
            u64 b0 = *(const u64*)&Bs[buf][kk][tx * 4];
            u64 b1 = *(const u64*)&Bs[buf][kk][tx * 4 + 2];
            u64 ap;
            asm("mov.b64 %0,{%1,%1};" : "=l"(ap) : "f"(av.x));
            asm("fma.rn.f32x2 %0,%1,%2,%0;" : "+l"(acc[0][0]) : "l"(ap), "l"(b0));
            asm("fma.rn.f32x2 %0,%1,%2,%0;" : "+l"(acc[0][1]) : "l"(ap), "l"(b1));
            asm("mov.b64 %0,{%1,%1};" : "=l"(ap) : "f"(av.y));
            asm("fma.rn.f32x2 %0,%1,%2,%0;" : "+l"(acc[1][0]) : "l"(ap), "l"(b0));
            asm("fma.rn.f32x2 %0,%1,%2,%0;" : "+l"(acc[1][1]) : "l"(ap), "l"(b1));
            asm("mov.b64 %0,{%1,%1};" : "=l"(ap) : "f"(av.z));
            asm("fma.rn.f32x2 %0,%1,%2,%0;" : "+l"(acc[2][0]) : "l"(ap), "l"(b0));
            asm("fma.rn.f32x2 %0,%1,%2,%0;" : "+l"(acc[2][1]) : "l"(ap), "l"(b1));
            asm("mov.b64 %0,{%1,%1};" : "=l"(ap) : "f"(av.w));
            asm("fma.rn.f32x2 %0,%1,%2,%0;" : "+l"(acc[3][0]) : "l"(ap), "l"(b0));
            asm("fma.rn.f32x2 %0,%1,%2,%0;" : "+l"(acc[3][1]) : "l"(ap), "l"(b1));
        }
        if (kt < KT - 1) {
            int nb = buf ^ 1;
            if (t < 128) {
                As[nb][lp+0][lr]=a4.x; As[nb][lp+1][lr]=a4.y; As[nb][lp+2][lr]=a4.z; As[nb][lp+3][lr]=a4.w;
                Bs[nb][lp+0][lr]=b4.x; Bs[nb][lp+1][lr]=b4.y; Bs[nb][lp+2][lr]=b4.z; Bs[nb][lp+3][lr]=b4.w;
            }
            buf = nb;
        }
        __syncthreads();
    }
    float* outp = g_hW + (size_t)ks * B_ * HH;
#pragma unroll
    for (int i = 0; i < 4; i++) {
        int row = m0 + ty * 4 + i;
#pragma unroll
        for (int jp = 0; jp < 2; jp++) {
            float l, hv;
            asm("mov.b64 {%0,%1},%2;" : "=f"(l), "=f"(hv) : "l"(acc[i][jp]));
            int c0 = n0 + tx * 4 + jp * 2;
            float bb0 = (ks == 0) ? be[c0] : 0.f;
            float bb1 = (ks == 0) ? be[c0 + 1] : 0.f;
            outp[row * HH + c0]     = l  + bb0;
            outp[row * HH + c0 + 1] = hv + bb1;
        }
    }
}

// ================== mma core: single-term fp16 ==================
// buffer: A(0..16K) BH(16K..32K); BUFSZ_S=32K, double-buffered
#define B_HI  16384u
#define BUFSZ_S 32768u

__device__ __forceinline__ void mma_chunk1(float acc[2][8][4], uint32_t bb,
                                           int wm, int wn, int lane) {
#pragma unroll
    for (int ks = 0; ks < 4; ks++) {
        uint32_t bh[4][4];
        int mm = lane >> 3, ch = mm & 1;
        int rhalf = ((mm >> 1) << 3) + (lane & 7);
#pragma unroll
        for (int p = 0; p < 4; p++) {
            uint32_t off = (uint32_t)(wn * 64 + p * 16 + rhalf) * 128 + ks * 32 + ch * 16;
            ldsm4(bh[p], bb + B_HI + swz(off));
        }
#pragma unroll
        for (int mt = 0; mt < 2; mt++) {
            uint32_t offa = (uint32_t)(wm * 32 + mt * 16 + (lane & 15)) * 128
                          + ks * 32 + (lane >> 4) * 16;
            uint32_t ah[4];
            ldsm4(ah, bb + swz(offa));
#pragma unroll
            for (int nt = 0; nt < 8; nt++)
                mma16816(acc[mt][nt], ah, &bh[nt >> 1][(nt & 1) * 2]);
        }
    }
}

// ---------------- kernel 2: scores GEMM (single-term fp16, occ 2) ----------------
// grid (4, 256): nq = 128-col quarter of U_e, b = batch. M = 128 objects, K=512.
__global__ void __launch_bounds__(256, 2)
k_scores_mma(const float* __restrict__ w) {
    extern __shared__ __align__(1024) char smem[];
    uint32_t S = smem_u32(smem);
    const int t = threadIdx.x, wid = t >> 5, lane = t & 31;
    const int wm = wid >> 1, wn = wid & 1;
    const int nq = blockIdx.x, b = blockIdx.y;
    const int n0 = nq * 128;

    const uint32_t OFF_HW = 0, OFF_W = 512, OFF_RS = 1024, OFF_BUF = 2048;
    float* hWs = (float*)(smem + OFF_HW);
    float* ws  = (float*)(smem + OFF_W);
    float* rs  = (float*)(smem + OFF_RS);

    if (t < 128) {
        int idx = b * HH + n0 + t;
        float s8 = 0.f;
#pragma unroll
        for (int sk = 0; sk < 8; sk++) s8 += g_hW[(size_t)sk * B_ * HH + idx];
        hWs[t] = s8;
        ws[t] = w[n0 + t];
    }

    const int row_ = t >> 1;                  // 0..127 (thread pairs per row)
    const int c8a = (t & 1) * 4;              // base 16B-chunk within row half
    auto prefetch = [&](int kc, int buf) {
        uint32_t Sb = S + OFF_BUF + buf * BUFSZ_S;
        const __half* Asrc = g_xjh + (size_t)(b * O_ + row_) * HH + kc * 64;
        const __half* BHsrc = g_UeH + (size_t)(n0 + row_) * HH + kc * 64;
#pragma unroll
        for (int j = 0; j < 4; j++) {
            uint32_t off = swz((uint32_t)row_ * 128 + (c8a + j) * 16);
            cp16(Sb + off,        Asrc + (c8a + j) * 8);
            cp16(Sb + B_HI + off, BHsrc + (c8a + j) * 8);
        }
        CP_COMMIT();
    };

    float acc[2][8][4] = {};
    prefetch(0, 0);
    for (int c = 0; c < 8; c++) {
        CP_WAIT0();
        __syncthreads();
        if (c + 1 < 8) prefetch(c + 1, (c + 1) & 1);
        mma_chunk1(acc, S + OFF_BUF + (c & 1) * BUFSZ_S, wm, wn, lane);
    }

    // epilogue: tanh(C + hW) * w, reduce over 128 cols
    int g = lane >> 2, q = lane & 3;
#pragma unroll
    for (int mt = 0; mt < 2; mt++) {
        float sA = 0.f, sB = 0.f;
#pragma unroll
        for (int nt = 0; nt < 8; nt++) {
            int col = wn * 64 + nt * 8 + q * 2;
            sA += tanhf(acc[mt][nt][0] + hWs[col])     * ws[col];
            sA += tanhf(acc[mt][nt][1] + hWs[col + 1]) * ws[col + 1];
            sB += tanhf(acc[mt][nt][2] + hWs[col])     * ws[col];
            sB += tanhf(acc[mt][nt][3] + hWs[col + 1]) * ws[col + 1];
        }
        sA += __shfl_xor_sync(0xffffffffu, sA, 1);
        sA += __shfl_xor_sync(0xffffffffu, sA, 2);
        sB += __shfl_xor_sync(0xffffffffu, sB, 1);
        sB += __shfl_xor_sync(0xffffffffu, sB, 2);
        if (q == 0) {
            int r0 = wm * 32 + mt * 16 + g;
            rs[wn * 128 + r0]     = sA;
            rs[wn * 128 + r0 + 8] = sB;
        }
    }
    __syncthreads();
    if (t < 128)
        g_partial[(b * O_ + t) * 4 + nq] = rs[t] + rs[128 + t];
}

// ---------------- kernel 3: fused softmax + phi + z-gather (512 threads, R12) -------
__global__ void __launch_bounds__(512, 2)
k_attn_z(const void* __restrict__ mask, const float* __restrict__ XF,
         const float* __restrict__ h, const float* __restrict__ c) {
    __shared__ float sa[128], redm[128], reds[128], phis[512];
    int b = blockIdx.x, t = threadIdx.x;  // 512 threads
    float s = 0.f, e = 0.f;
    if (t < 128) {
        const float* pr = g_partial + (b * O_ + t) * 4;
        s = pr[0] + pr[1] + pr[2] + pr[3];
        int mf = g_mflag;
        bool mv;
        int mi = b * O_ + t;
        if (mf == 1)      mv = ((const float*)mask)[mi] != 0.0f;
        else if (mf == 2) mv = ((const int*)mask)[mi] != 0;
        else              mv = ((const unsigned char*)mask)[mi] != 0;
        if (!mv) s = -1e9f;
        redm[t] = s;
    }
    __syncthreads();
    for (int off = 64; off > 0; off >>= 1) {
        if (t < off) redm[t] = fmaxf(redm[t], redm[t + off]);
        __syncthreads();
    }
    float mx = redm[0];
    if (t < 128) { e = expf(s - mx); reds[t] = e; }
    __syncthreads();
    for (int off = 64; off > 0; off >>= 1) {
        if (t < off) reds[t] += reds[t + off];
        __syncthreads();
    }
    if (t < 128) sa[t] = e / reds[0];
    __syncthreads();

    // phi: thread t owns column t (512 cols), fp16 x_j
    float acc = 0.f;
    const __half* X = g_xjh + (size_t)b * O_ * HH;
    for (int o = 0; o < O_; o++)
        acc += sa[o] * __half2float(X[(size_t)o * HH + t]);
    phis[t] = acc;
    __syncthreads();

    // z fp16: 8 elems per thread
    int j0 = t * 8;
    float v[8];
    if (j0 < 512) {
#pragma unroll
        for (int k = 0; k < 8; k++) v[k] = phis[j0 + k];
    } else if (j0 < 2048) {
        const float* p = XF + (size_t)b * DFF + (j0 - 512);
        float4 a = *(const float4*)p, bq = *(const float4*)(p + 4);
        v[0]=a.x; v[1]=a.y; v[2]=a.z; v[3]=a.w; v[4]=bq.x; v[5]=bq.y; v[6]=bq.z; v[7]=bq.w;
    } else if (j0 < 3072) {
        const float* p = h + (size_t)b * H_ + (j0 - 2048);
        float4 a = *(const float4*)p, bq = *(const float4*)(p + 4);
        v[0]=a.x; v[1]=a.y; v[2]=a.z; v[3]=a.w; v[4]=bq.x; v[5]=bq.y; v[6]=bq.z; v[7]=bq.w;
    } else {
        const float* p = c + (size_t)b * H_ + (j0 - 3072);
        float4 a = *(const float4*)p, bq = *(const float4*)(p + 4);
        v[0]=a.x; v[1]=a.y; v[2]=a.z; v[3]=a.w; v[4]=bq.x; v[5]=bq.y; v[6]=bq.z; v[7]=bq.w;
    }
    uint4 o;
    o.x = pk2(v[0], v[1]); o.y = pk2(v[2], v[3]);
    o.z = pk2(v[4], v[5]); o.w = pk2(v[6], v[7]);
    *(uint4*)(g_zh + (size_t)b * 4096 + j0) = o;
}

// ---------------- kernel 4: gates GEMM (single-term fp16 inline-B, split-K=4, occ 2)
// grid (32, 2, 4): bx = n-block(128), by = m-block(128), bz = K slice (1024)
__global__ void __launch_bounds__(256, 2)
k_gates_mma(const float* __restrict__ Wi, const float* __restrict__ Wf,
            const float* __restrict__ Wc, const float* __restrict__ Wo,
            const float* __restrict__ Ui, const float* __restrict__ Uf,
            const float* __restrict__ Uc, const float* __restrict__ Uo,
            const float* __restrict__ Vi, const float* __restrict__ Vf,
            const float* __restrict__ Vo) {
    extern __shared__ __align__(1024) char smem[];
    uint32_t S = smem_u32(smem);
    const int t = threadIdx.x, wid = t >> 5, lane = t & 31;
    const int wm = wid >> 1, wn = wid & 1;
    const int nb_ = blockIdx.x, mb = blockIdx.y, ksp = blockIdx.z;
    const int n0g = nb_ * 128;
    const int gg = n0g >> 10;
    const int jb = n0g & 1023;
    const float* Wg = (gg == 0) ? Wi : (gg == 1) ? Wf : (gg == 2) ? Wc : Wo;
    const float* Ug = (gg == 0) ? Ui : (gg == 1) ? Uf : (gg == 2) ? Uc : Uo;
    const float* Vg = (gg == 0) ? Vi : (gg == 1) ? Vf : (gg == 3) ? Vo : nullptr;

    const int row_ = t >> 1;
    const int c8a = (t & 1) * 4;
    auto prefetchA = [&](int kc, int buf) {
        uint32_t Sb = S + buf * BUFSZ_S;
        const __half* Asrc = g_zh + (size_t)(mb * 128 + row_) * 4096
                           + ksp * 1024 + kc * 64;
#pragma unroll
        for (int j = 0; j < 4; j++) {
            uint32_t off = swz((uint32_t)row_ * 128 + (c8a + j) * 16);
            cp16(Sb + off, Asrc + (c8a + j) * 8);
        }
        CP_COMMIT();
    };

    float4 pb[8];
    auto loadB = [&](int kc) {
        int kk0 = ksp * 1024 + kc * 64;
        const float* bp = nullptr; int rstride = 0; bool zer = false;
        if (kk0 < 2048)      { bp = Wg + kk0;          rstride = 2048; }
        else if (kk0 < 3072) { bp = Ug + (kk0 - 2048); rstride = 1024; }
        else if (Vg)         { bp = Vg + (kk0 - 3072); rstride = 1024; }
        else                 { zer = true; }
#pragma unroll
        for (int i = 0; i < 8; i++) {
            int idx = i * 256 + t, row = idx >> 4, f4 = idx & 15;
            pb[i] = zer ? make_float4(0, 0, 0, 0)
                        : *(const float4*)(bp + (size_t)(jb + row) * rstride + f4 * 4);
        }
    };
    auto stsB = [&](int buf) {
        char* base = smem + buf * BUFSZ_S;
#pragma unroll
        for (int i = 0; i < 8; i++) {
            int idx = i * 256 + t, row = idx >> 4, f4 = idx & 15;
            cvt_f16h(base + B_HI, (uint32_t)row * 128 + f4 * 8, pb[i]);
        }
    };

    float acc[2][8][4] = {};
    loadB(0);
    stsB(0);
    prefetchA(0, 0);
    for (int c = 0; c < 16; c++) {
        CP_WAIT0();
        __syncthreads();
        if (c + 1 < 16) { loadB(c + 1); prefetchA(c + 1, (c + 1) & 1); }
        mma_chunk1(acc, S + (c & 1) * BUFSZ_S, wm, wn, lane);
        if (c + 1 < 16) stsB((c + 1) & 1);
    }

    // epilogue: store fp32 partials
    int g = lane >> 2, q = lane & 3;
#pragma unroll
    for (int mt = 0; mt < 2; mt++) {
        int m = mb * 128 + wm * 32 + mt * 16 + g;
        float* baseA = g_gp + (size_t)(ksp * B_ + m) * 4096 + n0g;
        float* baseB = g_gp + (size_t)(ksp * B_ + m + 8) * 4096 + n0g;
#pragma unroll
        for (int nt = 0; nt < 8; nt++) {
            int col = wn * 64 + nt * 8 + q * 2;
            *(float2*)(baseA + col) = make_float2(acc[mt][nt][0], acc[mt][nt][1]);
            *(float2*)(baseB + col) = make_float2(acc[mt][nt][2], acc[mt][nt][3]);
        }
    }
}

// ---------------- kernel 5: elementwise LSTM update ----------------
__global__ void k_final(const float* __restrict__ c,
                        const float* __restrict__ bi, const float* __restrict__ bf,
                        const float* __restrict__ bc, const float* __restrict__ bo,
                        float* __restrict__ out) {
    int idx = blockIdx.x * 256 + threadIdx.x;
    int b = idx >> 10, j = idx & 1023;
    const float* g0 = g_gp + (size_t)b * 4096;
    const float* g1 = g_gp + (size_t)(B_ + b) * 4096;
    const float* g2 = g_gp + (size_t)(2 * B_ + b) * 4096;
    const float* g3 = g_gp + (size_t)(3 * B_ + b) * 4096;
    float gi = g0[j]        + g1[j]        + g2[j]        + g3[j]        + bi[j];
    float gf = g0[1024 + j] + g1[1024 + j] + g2[1024 + j] + g3[1024 + j] + bf[j];
    float gc = g0[2048 + j] + g1[2048 + j] + g2[2048 + j] + g3[2048 + j] + bc[j];
    float go = g0[3072 + j] + g1[3072 + j] + g2[3072 + j] + g3[3072 + j] + bo[j];
    float si = sigmoidf_(gi);
    float sf = sigmoidf_(gf);
    float so = sigmoidf_(go);
    float cold = c[idx];
    float nc = sf * cold + si * tanhf(gc);
    float nh = so * tanhf(nc);
    out[idx] = nh;
    out[B_ * H_ + idx] = nc;
}

// ---------------- launch ----------------
extern "C" void kernel_launch(void* const* d_in, const int* in_sizes, int n_in,
                              void* d_out, int out_size) {
    const float* x_j  = (const float*)d_in[0];
    const void*  mask = d_in[1];
    const float* X_F  = (const float*)d_in[2];
    const float* h    = (const float*)d_in[3];
    const float* c    = (const float*)d_in[4];
    const float* W_i  = (const float*)d_in[5];
    const float* W_f  = (const float*)d_in[6];
    const float* W_c  = (const float*)d_in[7];
    const float* W_o  = (const float*)d_in[8];
    const float* U_i  = (const float*)d_in[9];
    const float* U_f  = (const float*)d_in[10];
    const float* U_c  = (const float*)d_in[11];
    const float* U_o  = (const float*)d_in[12];
    const float* V_i  = (const float*)d_in[13];
    const float* V_f  = (const float*)d_in[14];
    const float* V_o  = (const float*)d_in[16];
    const float* b_i  = (const float*)d_in[17];
    const float* b_f  = (const float*)d_in[18];
    const float* b_c  = (const float*)d_in[19];
    const float* b_o  = (const float*)d_in[20];
    const float* w    = (const float*)d_in[21];
    const float* W_e  = (const float*)d_in[22];
    const float* U_e  = (const float*)d_in[23];
    const float* b_e  = (const float*)d_in[24];

    cudaFuncSetAttribute(k_scores_mma, cudaFuncAttributeMaxDynamicSharedMemorySize, 67584);
    cudaFuncSetAttribute(k_gates_mma,  cudaFuncAttributeMaxDynamicSharedMemorySize, 65536);

    k_pre<<<8577, 256>>>(x_j, U_e, h, W_e, b_e, (const unsigned char*)mask);
    k_scores_mma<<<dim3(4, 256), 256, 67584>>>(w);
    k_attn_z<<<256, 512>>>(mask, X_F, h, c);
    k_gates_mma<<<dim3(32, 2, 4), 256, 65536>>>(W_i, W_f, W_c, W_o,
                                                U_i, U_f, U_c, U_o,
                                                V_i, V_f, V_o);
    k_final<<<1024, 256>>>(c, b_i, b_f, b_c, b_o, (float*)d_out);
}

// round 17
// speedup vs baseline: 1.1534x; 1.0767x over previous
#include <cuda_runtime.h>
#include <cuda_fp16.h>
#include <cstdint>

// Problem constants
#define B_  256
#define O_  128
#define H_  1024
#define HH  512
#define I_  2048
#define DFF 1536

typedef unsigned long long u64;

// ---------------- device scratch ----------------
__device__ __align__(16) float g_hW[8 * B_ * HH];      // split-K=8 partials of h@W_e^T (+b_e slice0)
__device__ __align__(16) float g_partial[B_ * O_ * 4]; // score partials
__device__ __align__(16) __half g_xjh[B_ * O_ * HH];   // x_j in fp16 (32MB)
__device__ __align__(16) __half g_UeH[HH * HH];        // U_e fp16
__device__ __align__(16) __half g_zh[B_ * 4096];       // [phi|X_F|h|c] fp16
__device__ __align__(16) float g_gp[4 * B_ * 4096];    // split-K=4 gate partials
__device__ int g_mflag;

// ---------------- helpers ----------------
__device__ __forceinline__ uint32_t smem_u32(const void* p) {
    uint32_t a;
    asm("{ .reg .u64 t; cvta.to.shared.u64 t, %1; cvt.u32.u64 %0, t; }" : "=r"(a) : "l"(p));
    return a;
}
__device__ __forceinline__ uint32_t swz(uint32_t off) { return off ^ ((off >> 3) & 0x70); }

__device__ __forceinline__ void ldsm4(uint32_t* r, uint32_t addr) {
    asm volatile("ldmatrix.sync.aligned.m8n8.x4.shared.b16 {%0,%1,%2,%3},[%4];"
        : "=r"(r[0]), "=r"(r[1]), "=r"(r[2]), "=r"(r[3]) : "r"(addr));
}
__device__ __forceinline__ void mma16816(float* c, const uint32_t* a, const uint32_t* b) {
    asm volatile("mma.sync.aligned.m16n8k16.row.col.f32.f16.f16.f32 "
        "{%0,%1,%2,%3},{%4,%5,%6,%7},{%8,%9},{%0,%1,%2,%3};"
        : "+f"(c[0]), "+f"(c[1]), "+f"(c[2]), "+f"(c[3])
        : "r"(a[0]), "r"(a[1]), "r"(a[2]), "r"(a[3]), "r"(b[0]), "r"(b[1]));
}
__device__ __forceinline__ void cp16(uint32_t dst, const void* src) {
    asm volatile("cp.async.cg.shared.global [%0],[%1],16;" :: "r"(dst), "l"(src));
}
#define CP_COMMIT() asm volatile("cp.async.commit_group;" ::: "memory")
#define CP_WAIT0()  asm volatile("cp.async.wait_group 0;" ::: "memory")

__device__ __forceinline__ uint32_t pk2(float a, float b) {
    __half2 x = __floats2half2_rn(a, b);
    uint32_t r; memcpy(&r, &x, 4); return r;
}
__device__ __forceinline__ float sigmoidf_(float x) { return 1.0f / (1.0f + expf(-x)); }

// fp16 (round-nearest) of a float4, stored swizzled as u64
__device__ __forceinline__ void cvt_f16h(char* hib, uint32_t off, float4 v) {
    uint32_t so = swz(off);
    uint32_t h0 = pk2(v.x, v.y);
    uint32_t h1 = pk2(v.z, v.w);
    *(u64*)(hib + so) = (u64)h0 | ((u64)h1 << 32);
}

// ---------------- kernel 0: sniff mask dtype ----------------
__global__ void k_sniff(const unsigned char* __restrict__ m) {
    __shared__ int anyBig, off123;
    if (threadIdx.x == 0) { anyBig = 0; off123 = 0; }
    __syncthreads();
    int big = 0, o123 = 0;
    for (int i = threadIdx.x; i < 4096; i += blockDim.x) {
        unsigned char v = m[i];
        if (v >= 2) big = 1;
        if ((i & 3) != 0 && v != 0) o123 = 1;
    }
    if (big) atomicOr(&anyBig, 1);
    if (o123) atomicOr(&off123, 1);
    __syncthreads();
    if (threadIdx.x == 0) g_mflag = anyBig ? 1 : (off123 ? 0 : 2);
}

// ---------------- conversion kernels ----------------
__global__ void k_cvt_xj(const float* __restrict__ xj) {
    size_t i = ((size_t)blockIdx.x * 256 + threadIdx.x) * 8;
    float4 v0 = *(const float4*)(xj + i);
    float4 v1 = *(const float4*)(xj + i + 4);
    uint4 o;
    o.x = pk2(v0.x, v0.y); o.y = pk2(v0.z, v0.w);
    o.z = pk2(v1.x, v1.y); o.w = pk2(v1.z, v1.w);
    *(uint4*)(g_xjh + i) = o;
}
__global__ void k_cvt_ue(const float* __restrict__ Ue) {
    size_t i = ((size_t)blockIdx.x * 256 + threadIdx.x) * 8;
    float4 v0 = *(const float4*)(Ue + i);
    float4 v1 = *(const float4*)(Ue + i + 4);
    uint4 hi;
    hi.x = pk2(v0.x, v0.y); hi.y = pk2(v0.z, v0.w);
    hi.z = pk2(v1.x, v1.y); hi.w = pk2(v1.z, v1.w);
    *(uint4*)(g_UeH + i) = hi;
}

// ---------------- kernel 1: g_hW partials = h @ W_e^T (split-K=8) ----------------
// grid (8, 4, 8): n-tile 64, m-tile 64, K slice 128. Slice 0 adds b_e.
__global__ void __launch_bounds__(256, 2)
k_hW(const float* __restrict__ h, const float* __restrict__ We,
     const float* __restrict__ be) {
    __shared__ __align__(16) float As[2][8][64];
    __shared__ __align__(16) float Bs[2][8][64];
    int t = threadIdx.x;
    int m0 = blockIdx.y * 64, n0 = blockIdx.x * 64;
    int ks = blockIdx.z;
    int tx = t & 15, ty = t >> 4;
    int lr = t >> 1, lp = (t & 1) * 4;
    const float* Ap = h  + (m0 + lr) * H_ + ks * 128 + lp;
    const float* Bp = We + (n0 + lr) * H_ + ks * 128 + lp;

    u64 acc[4][2] = {};
    float4 a4 = make_float4(0,0,0,0), b4 = make_float4(0,0,0,0);
    if (t < 128) { a4 = *(const float4*)Ap; b4 = *(const float4*)Bp; }
    if (t < 128) {
        As[0][lp+0][lr]=a4.x; As[0][lp+1][lr]=a4.y; As[0][lp+2][lr]=a4.z; As[0][lp+3][lr]=a4.w;
        Bs[0][lp+0][lr]=b4.x; Bs[0][lp+1][lr]=b4.y; Bs[0][lp+2][lr]=b4.z; Bs[0][lp+3][lr]=b4.w;
    }
    __syncthreads();
    int buf = 0;
    const int KT = 128 / 8;
    for (int kt = 0; kt < KT; kt++) {
        if (kt < KT - 1 && t < 128) {
            a4 = *(const float4*)(Ap + (kt + 1) * 8);
            b4 = *(const float4*)(Bp + (kt + 1) * 8);
        }
#pragma unroll
        for (int kk = 0; kk < 8; kk++) {
            float4 av = *(const float4*)&As[buf][kk][ty * 4];
            u64 b0 = *(const u64*)&Bs[buf][kk][tx * 4];
            u64 b1 = *(const u64*)&Bs[buf][kk][tx * 4 + 2];
            u64 ap;
            asm("mov.b64 %0,{%1,%1};" : "=l"(ap) : "f"(av.x));
            asm("fma.rn.f32x2 %0,%1,%2,%0;" : "+l"(acc[0][0]) : "l"(ap), "l"(b0));
            asm("fma.rn.f32x2 %0,%1,%2,%0;" : "+l"(acc[0][1]) : "l"(ap), "l"(b1));
            asm("mov.b64 %0,{%1,%1};" : "=l"(ap) : "f"(av.y));
            asm("fma.rn.f32x2 %0,%1,%2,%0;" : "+l"(acc[1][0]) : "l"(ap), "l"(b0));
            asm("fma.rn.f32x2 %0,%1,%2,%0;" : "+l"(acc[1][1]) : "l"(ap), "l"(b1));
            asm("mov.b64 %0,{%1,%1};" : "=l"(ap) : "f"(av.z));
            asm("fma.rn.f32x2 %0,%1,%2,%0;" : "+l"(acc[2][0]) : "l"(ap), "l"(b0));
            asm("fma.rn.f32x2 %0,%1,%2,%0;" : "+l"(acc[2][1]) : "l"(ap), "l"(b1));
            asm("mov.b64 %0,{%1,%1};" : "=l"(ap) : "f"(av.w));
            asm("fma.rn.f32x2 %0,%1,%2,%0;" : "+l"(acc[3][0]) : "l"(ap), "l"(b0));
            asm("fma.rn.f32x2 %0,%1,%2,%0;" : "+l"(acc[3][1]) : "l"(ap), "l"(b1));
        }
        if (kt < KT - 1) {
            int nb = buf ^ 1;
            if (t < 128) {
                As[nb][lp+0][lr]=a4.x; As[nb][lp+1][lr]=a4.y; As[nb][lp+2][lr]=a4.z; As[nb][lp+3][lr]=a4.w;
                Bs[nb][lp+0][lr]=b4.x; Bs[nb][lp+1][lr]=b4.y; Bs[nb][lp+2][lr]=b4.z; Bs[nb][lp+3][lr]=b4.w;
            }
            buf = nb;
        }
        __syncthreads();
    }
    float* outp = g_hW + (size_t)ks * B_ * HH;
#pragma unroll
    for (int i = 0; i < 4; i++) {
        int row = m0 + ty * 4 + i;
#pragma unroll
        for (int jp = 0; jp < 2; jp++) {
            float l, hv;
            asm("mov.b64 {%0,%1},%2;" : "=f"(l), "=f"(hv) : "l"(acc[i][jp]));
            int c0 = n0 + tx * 4 + jp * 2;
            float bb0 = (ks == 0) ? be[c0] : 0.f;
            float bb1 = (ks == 0) ? be[c0 + 1] : 0.f;
            outp[row * HH + c0]     = l  + bb0;
            outp[row * HH + c0 + 1] = hv + bb1;
        }
    }
}

// ================== mma core: single-term fp16 ==================
// buffer: A(0..16K) BH(16K..32K); BUFSZ_S=32K, double-buffered
#define B_HI  16384u
#define BUFSZ_S 32768u

__device__ __forceinline__ void mma_chunk1(float acc[2][8][4], uint32_t bb,
                                           int wm, int wn, int lane) {
#pragma unroll
    for (int ks = 0; ks < 4; ks++) {
        uint32_t bh[4][4];
        int mm = lane >> 3, ch = mm & 1;
        int rhalf = ((mm >> 1) << 3) + (lane & 7);
#pragma unroll
        for (int p = 0; p < 4; p++) {
            uint32_t off = (uint32_t)(wn * 64 + p * 16 + rhalf) * 128 + ks * 32 + ch * 16;
            ldsm4(bh[p], bb + B_HI + swz(off));
        }
#pragma unroll
        for (int mt = 0; mt < 2; mt++) {
            uint32_t offa = (uint32_t)(wm * 32 + mt * 16 + (lane & 15)) * 128
                          + ks * 32 + (lane >> 4) * 16;
            uint32_t ah[4];
            ldsm4(ah, bb + swz(offa));
#pragma unroll
            for (int nt = 0; nt < 8; nt++)
                mma16816(acc[mt][nt], ah, &bh[nt >> 1][(nt & 1) * 2]);
        }
    }
}

// ---------------- kernel 2: scores GEMM (single-term fp16, occ 2) ----------------
// grid (4, 256): nq = 128-col quarter of U_e, b = batch. M = 128 objects, K=512.
__global__ void __launch_bounds__(256, 2)
k_scores_mma(const float* __restrict__ w) {
    extern __shared__ __align__(1024) char smem[];
    uint32_t S = smem_u32(smem);
    const int t = threadIdx.x, wid = t >> 5, lane = t & 31;
    const int wm = wid >> 1, wn = wid & 1;
    const int nq = blockIdx.x, b = blockIdx.y;
    const int n0 = nq * 128;

    const uint32_t OFF_HW = 0, OFF_W = 512, OFF_RS = 1024, OFF_BUF = 2048;
    float* hWs = (float*)(smem + OFF_HW);
    float* ws  = (float*)(smem + OFF_W);
    float* rs  = (float*)(smem + OFF_RS);

    if (t < 128) {
        int idx = b * HH + n0 + t;
        float s8 = 0.f;
#pragma unroll
        for (int sk = 0; sk < 8; sk++) s8 += g_hW[(size_t)sk * B_ * HH + idx];
        hWs[t] = s8;
        ws[t] = w[n0 + t];
    }

    const int row_ = t >> 1;                  // 0..127 (thread pairs per row)
    const int c8a = (t & 1) * 4;              // base 16B-chunk within row half
    auto prefetch = [&](int kc, int buf) {
        uint32_t Sb = S + OFF_BUF + buf * BUFSZ_S;
        const __half* Asrc = g_xjh + (size_t)(b * O_ + row_) * HH + kc * 64;
        const __half* BHsrc = g_UeH + (size_t)(n0 + row_) * HH + kc * 64;
#pragma unroll
        for (int j = 0; j < 4; j++) {
            uint32_t off = swz((uint32_t)row_ * 128 + (c8a + j) * 16);
            cp16(Sb + off,        Asrc + (c8a + j) * 8);
            cp16(Sb + B_HI + off, BHsrc + (c8a + j) * 8);
        }
        CP_COMMIT();
    };

    float acc[2][8][4] = {};
    prefetch(0, 0);
    for (int c = 0; c < 8; c++) {
        CP_WAIT0();
        __syncthreads();
        if (c + 1 < 8) prefetch(c + 1, (c + 1) & 1);
        mma_chunk1(acc, S + OFF_BUF + (c & 1) * BUFSZ_S, wm, wn, lane);
    }

    // epilogue: tanh(C + hW) * w, reduce over 128 cols
    int g = lane >> 2, q = lane & 3;
#pragma unroll
    for (int mt = 0; mt < 2; mt++) {
        float sA = 0.f, sB = 0.f;
#pragma unroll
        for (int nt = 0; nt < 8; nt++) {
            int col = wn * 64 + nt * 8 + q * 2;
            sA += tanhf(acc[mt][nt][0] + hWs[col])     * ws[col];
            sA += tanhf(acc[mt][nt][1] + hWs[col + 1]) * ws[col + 1];
            sB += tanhf(acc[mt][nt][2] + hWs[col])     * ws[col];
            sB += tanhf(acc[mt][nt][3] + hWs[col + 1]) * ws[col + 1];
        }
        sA += __shfl_xor_sync(0xffffffffu, sA, 1);
        sA += __shfl_xor_sync(0xffffffffu, sA, 2);
        sB += __shfl_xor_sync(0xffffffffu, sB, 1);
        sB += __shfl_xor_sync(0xffffffffu, sB, 2);
        if (q == 0) {
            int r0 = wm * 32 + mt * 16 + g;
            rs[wn * 128 + r0]     = sA;
            rs[wn * 128 + r0 + 8] = sB;
        }
    }
    __syncthreads();
    if (t < 128)
        g_partial[(b * O_ + t) * 4 + nq] = rs[t] + rs[128 + t];
}

// ---------------- kernel 3: fused softmax + phi + z-gather (fp16 out) ----------------
__global__ void __launch_bounds__(512, 2)
k_attn_z(const void* __restrict__ mask, const float* __restrict__ XF,
         const float* __restrict__ h, const float* __restrict__ c) {
    __shared__ float sa[128], redm[128], reds[128], phis[512];
    int b = blockIdx.x, t = threadIdx.x;  // 512 threads
    float s = 0.f, e = 0.f;
    if (t < 128) {
        const float* pr = g_partial + (b * O_ + t) * 4;
        s = pr[0] + pr[1] + pr[2] + pr[3];
        int mf = g_mflag;
        bool mv;
        int mi = b * O_ + t;
        if (mf == 1)      mv = ((const float*)mask)[mi] != 0.0f;
        else if (mf == 2) mv = ((const int*)mask)[mi] != 0;
        else              mv = ((const unsigned char*)mask)[mi] != 0;
        if (!mv) s = -1e9f;
        redm[t] = s;
    }
    __syncthreads();
    for (int off = 64; off > 0; off >>= 1) {
        if (t < off) redm[t] = fmaxf(redm[t], redm[t + off]);
        __syncthreads();
    }
    float mx = redm[0];
    if (t < 128) { e = expf(s - mx); reds[t] = e; }
    __syncthreads();
    for (int off = 64; off > 0; off >>= 1) {
        if (t < off) reds[t] += reds[t + off];
        __syncthreads();
    }
    if (t < 128) sa[t] = e / reds[0];
    __syncthreads();

    // phi: thread t owns column t (512 cols), fp16 x_j
    float acc = 0.f;
    const __half* X = g_xjh + (size_t)b * O_ * HH;
    for (int o = 0; o < O_; o++)
        acc += sa[o] * __half2float(X[(size_t)o * HH + t]);
    phis[t] = acc;
    __syncthreads();

    // z fp16: 8 elems per thread
    int j0 = t * 8;
    float v[8];
    if (j0 < 512) {
#pragma unroll
        for (int k = 0; k < 8; k++) v[k] = phis[j0 + k];
    } else if (j0 < 2048) {
        const float* p = XF + (size_t)b * DFF + (j0 - 512);
        float4 a = *(const float4*)p, bq = *(const float4*)(p + 4);
        v[0]=a.x; v[1]=a.y; v[2]=a.z; v[3]=a.w; v[4]=bq.x; v[5]=bq.y; v[6]=bq.z; v[7]=bq.w;
    } else if (j0 < 3072) {
        const float* p = h + (size_t)b * H_ + (j0 - 2048);
        float4 a = *(const float4*)p, bq = *(const float4*)(p + 4);
        v[0]=a.x; v[1]=a.y; v[2]=a.z; v[3]=a.w; v[4]=bq.x; v[5]=bq.y; v[6]=bq.z; v[7]=bq.w;
    } else {
        const float* p = c + (size_t)b * H_ + (j0 - 3072);
        float4 a = *(const float4*)p, bq = *(const float4*)(p + 4);
        v[0]=a.x; v[1]=a.y; v[2]=a.z; v[3]=a.w; v[4]=bq.x; v[5]=bq.y; v[6]=bq.z; v[7]=bq.w;
    }
    uint4 o;
    o.x = pk2(v[0], v[1]); o.y = pk2(v[2], v[3]);
    o.z = pk2(v[4], v[5]); o.w = pk2(v[6], v[7]);
    *(uint4*)(g_zh + (size_t)b * 4096 + j0) = o;
}

// ---------------- kernel 4: gates GEMM (single-term fp16, split-K=4, occ 2) ---------
// grid (32, 2, 4): bx = n-block(128), by = m-block(128), bz = K slice (1024)
__global__ void __launch_bounds__(256, 2)
k_gates_mma(const float* __restrict__ Wi, const float* __restrict__ Wf,
            const float* __restrict__ Wc, const float* __restrict__ Wo,
            const float* __restrict__ Ui, const float* __restrict__ Uf,
            const float* __restrict__ Uc, const float* __restrict__ Uo,
            const float* __restrict__ Vi, const float* __restrict__ Vf,
            const float* __restrict__ Vo) {
    extern __shared__ __align__(1024) char smem[];
    uint32_t S = smem_u32(smem);
    const int t = threadIdx.x, wid = t >> 5, lane = t & 31;
    const int wm = wid >> 1, wn = wid & 1;
    const int nb_ = blockIdx.x, mb = blockIdx.y, ksp = blockIdx.z;
    const int n0g = nb_ * 128;
    const int gg = n0g >> 10;
    const int jb = n0g & 1023;
    const float* Wg = (gg == 0) ? Wi : (gg == 1) ? Wf : (gg == 2) ? Wc : Wo;
    const float* Ug = (gg == 0) ? Ui : (gg == 1) ? Uf : (gg == 2) ? Uc : Uo;
    const float* Vg = (gg == 0) ? Vi : (gg == 1) ? Vf : (gg == 3) ? Vo : nullptr;

    const int row_ = t >> 1;
    const int c8a = (t & 1) * 4;
    auto prefetchA = [&](int kc, int buf) {
        uint32_t Sb = S + buf * BUFSZ_S;
        const __half* Asrc = g_zh + (size_t)(mb * 128 + row_) * 4096
                           + ksp * 1024 + kc * 64;
#pragma unroll
        for (int j = 0; j < 4; j++) {
            uint32_t off = swz((uint32_t)row_ * 128 + (c8a + j) * 16);
            cp16(Sb + off, Asrc + (c8a + j) * 8);
        }
        CP_COMMIT();
    };

    float4 pb[8];
    auto loadB = [&](int kc) {
        int kk0 = ksp * 1024 + kc * 64;
        const float* bp = nullptr; int rstride = 0; bool zer = false;
        if (kk0 < 2048)      { bp = Wg + kk0;          rstride = 2048; }
        else if (kk0 < 3072) { bp = Ug + (kk0 - 2048); rstride = 1024; }
        else if (Vg)         { bp = Vg + (kk0 - 3072); rstride = 1024; }
        else                 { zer = true; }
#pragma unroll
        for (int i = 0; i < 8; i++) {
            int idx = i * 256 + t, row = idx >> 4, f4 = idx & 15;
            pb[i] = zer ? make_float4(0, 0, 0, 0)
                        : *(const float4*)(bp + (size_t)(jb + row) * rstride + f4 * 4);
        }
    };
    auto stsB = [&](int buf) {
        char* base = smem + buf * BUFSZ_S;
#pragma unroll
        for (int i = 0; i < 8; i++) {
            int idx = i * 256 + t, row = idx >> 4, f4 = idx & 15;
            cvt_f16h(base + B_HI, (uint32_t)row * 128 + f4 * 8, pb[i]);
        }
    };

    float acc[2][8][4] = {};
    loadB(0);
    stsB(0);
    prefetchA(0, 0);
    for (int c = 0; c < 16; c++) {
        CP_WAIT0();
        __syncthreads();
        if (c + 1 < 16) { loadB(c + 1); prefetchA(c + 1, (c + 1) & 1); }
        mma_chunk1(acc, S + (c & 1) * BUFSZ_S, wm, wn, lane);
        if (c + 1 < 16) stsB((c + 1) & 1);
    }

    // epilogue: store fp32 partials
    int g = lane >> 2, q = lane & 3;
#pragma unroll
    for (int mt = 0; mt < 2; mt++) {
        int m = mb * 128 + wm * 32 + mt * 16 + g;
        float* baseA = g_gp + (size_t)(ksp * B_ + m) * 4096 + n0g;
        float* baseB = g_gp + (size_t)(ksp * B_ + m + 8) * 4096 + n0g;
#pragma unroll
        for (int nt = 0; nt < 8; nt++) {
            int col = wn * 64 + nt * 8 + q * 2;
            *(float2*)(baseA + col) = make_float2(acc[mt][nt][0], acc[mt][nt][1]);
            *(float2*)(baseB + col) = make_float2(acc[mt][nt][2], acc[mt][nt][3]);
        }
    }
}

// ---------------- kernel 5: elementwise LSTM update ----------------
__global__ void k_final(const float* __restrict__ c,
                        const float* __restrict__ bi, const float* __restrict__ bf,
                        const float* __restrict__ bc, const float* __restrict__ bo,
                        float* __restrict__ out) {
    int idx = blockIdx.x * 256 + threadIdx.x;
    int b = idx >> 10, j = idx & 1023;
    const float* g0 = g_gp + (size_t)b * 4096;
    const float* g1 = g_gp + (size_t)(B_ + b) * 4096;
    const float* g2 = g_gp + (size_t)(2 * B_ + b) * 4096;
    const float* g3 = g_gp + (size_t)(3 * B_ + b) * 4096;
    float gi = g0[j]        + g1[j]        + g2[j]        + g3[j]        + bi[j];
    float gf = g0[1024 + j] + g1[1024 + j] + g2[1024 + j] + g3[1024 + j] + bf[j];
    float gc = g0[2048 + j] + g1[2048 + j] + g2[2048 + j] + g3[2048 + j] + bc[j];
    float go = g0[3072 + j] + g1[3072 + j] + g2[3072 + j] + g3[3072 + j] + bo[j];
    float si = sigmoidf_(gi);
    float sf = sigmoidf_(gf);
    float so = sigmoidf_(go);
    float cold = c[idx];
    float nc = sf * cold + si * tanhf(gc);
    float nh = so * tanhf(nc);
    out[idx] = nh;
    out[B_ * H_ + idx] = nc;
}

// ---------------- launch ----------------
extern "C" void kernel_launch(void* const* d_in, const int* in_sizes, int n_in,
                              void* d_out, int out_size) {
    const float* x_j  = (const float*)d_in[0];
    const void*  mask = d_in[1];
    const float* X_F  = (const float*)d_in[2];
    const float* h    = (const float*)d_in[3];
    const float* c    = (const float*)d_in[4];
    const float* W_i  = (const float*)d_in[5];
    const float* W_f  = (const float*)d_in[6];
    const float* W_c  = (const float*)d_in[7];
    const float* W_o  = (const float*)d_in[8];
    const float* U_i  = (const float*)d_in[9];
    const float* U_f  = (const float*)d_in[10];
    const float* U_c  = (const float*)d_in[11];
    const float* U_o  = (const float*)d_in[12];
    const float* V_i  = (const float*)d_in[13];
    const float* V_f  = (const float*)d_in[14];
    const float* V_o  = (const float*)d_in[16];
    const float* b_i  = (const float*)d_in[17];
    const float* b_f  = (const float*)d_in[18];
    const float* b_c  = (const float*)d_in[19];
    const float* b_o  = (const float*)d_in[20];
    const float* w    = (const float*)d_in[21];
    const float* W_e  = (const float*)d_in[22];
    const float* U_e  = (const float*)d_in[23];
    const float* b_e  = (const float*)d_in[24];

    cudaFuncSetAttribute(k_scores_mma, cudaFuncAttributeMaxDynamicSharedMemorySize, 67584);
    cudaFuncSetAttribute(k_gates_mma,  cudaFuncAttributeMaxDynamicSharedMemorySize, 65536);

    k_sniff<<<1, 256>>>((const unsigned char*)mask);
    k_cvt_xj<<<8192, 256>>>(x_j);
    k_cvt_ue<<<128, 256>>>(U_e);
    k_hW<<<dim3(8, 4, 8), 256>>>(h, W_e, b_e);
    k_scores_mma<<<dim3(4, 256), 256, 67584>>>(w);
    k_attn_z<<<256, 512>>>(mask, X_F, h, c);
    k_gates_mma<<<dim3(32, 2, 4), 256, 65536>>>(W_i, W_f, W_c, W_o,
                                                U_i, U_f, U_c, U_o,
                                                V_i, V_f, V_o);
    k_final<<<1024, 256>>>(c, b_i, b_f, b_c, b_o, (float*)d_out);
}